// round 12
// baseline (speedup 1.0000x reference)
#include <cuda_runtime.h>

// SamplingLayer: out[b, p*64+k] = sum_l x[b, p*1024+l] * exp(-((l+1)-w_k)^2/100)
// Gaussian band (std=10). Per k-PAIR union window of 80 floats, one x-load
// stream feeds two k's. W regenerated in registers via packed f32x2
// multiplicative recurrence (zero W memory traffic):
//   W2=(w_j,w_{j+1}); S2=(q_j q_{j+1}, q_{j+1} q_{j+2}); W2*=S2; S2*=r^4.
// R11: 512 threads/block (1 row x 1 k-pair per thread) at unchanged smem ->
// 48 warps/SM (75% occ) to cover memory latency (R10 was latency-bound at
// 36% occ with every pipe <60%).

#define NUM_P   8
#define DLEN    1024
#define KT      64          // L_tilde
#define WS      64          // core window per k
#define ULEN    80          // union window per k-pair (floats)
#define UJ      (ULEN/4)    // 20 float4 steps
#define ROWS    16          // (b,p) rows per block tile
#define STRIDE  1028        // padded smem row stride (==4 mod 32, phase-conflict-free)
#define OSTRIDE 68          // padded output staging stride
#define THREADS 512

__device__ float4 g_init[KT];     // per k: (w0, w0*q0, q0^2*r, q0^2*r^3) seeded at ubase
__device__ int    g_ubase[KT/2];  // per k-pair union base

// Precompute union bases + packed recurrence seeds. Deterministic, re-run
// every launch; trivial cost.
__global__ void precompute_kernel(const float* __restrict__ w) {
    __shared__ int bases[KT];
    int k = threadIdx.x;
    float wk = w[k];
    int base = (int)rintf(wk) - 33;           // center 64-window: t = base+1..base+64
    base &= ~3;                                // 16B alignment
    base = max(0, min(base, DLEN - WS));
    bases[k] = base;
    __syncthreads();
    int kg = k >> 1;
    int ub = min(bases[kg * 2], DLEN - ULEN);  // union covers both pair members
    if ((k & 1) == 0) g_ubase[kg] = ub;
    float d0 = (float)(ub + 1) - wk;
    float w0 = expf(-d0 * d0 * 0.01f);
    float q0 = expf(-(2.0f * d0 + 1.0f) * 0.01f);
    const float r = 0.98019867330675525f;      // exp(-0.02)
    float s0 = q0 * q0 * r;                    // q_0*q_1
    float s1 = s0 * r * r;                     // q_1*q_2
    g_init[k] = make_float4(w0, w0 * q0, s0, s1);
}

__device__ __forceinline__ unsigned long long pack2(float lo, float hi) {
    return ((unsigned long long)__float_as_uint(hi) << 32) |
           (unsigned long long)__float_as_uint(lo);
}
__device__ __forceinline__ float hsum2(unsigned long long v) {
    return __uint_as_float((unsigned int)v) + __uint_as_float((unsigned int)(v >> 32));
}

__global__ void __launch_bounds__(THREADS, 3)
sampling_main_kernel(const float* __restrict__ x, float* __restrict__ out) {
    __shared__ __align__(16) float x_s[ROWS * STRIDE];   // 65792 B
    __shared__ float4 init_s[KT];
    __shared__ int    ub_s[KT / 2];

    const int t = threadIdx.x;
    const size_t tile = blockIdx.x;

    // ---- stage x tile: 16 contiguous (b,p) rows, fully coalesced float4 loads ----
    const float4* __restrict__ xg = (const float4*)(x + tile * (size_t)(ROWS * DLEN));
    #pragma unroll
    for (int i = 0; i < (ROWS * DLEN / 4) / THREADS; i++) {  // 8 iters
        int idx = t + i * THREADS;
        int row = idx >> 8;          // 256 float4 per row
        int c4  = idx & 255;
        float4 v = xg[idx];
        *(float4*)&x_s[row * STRIDE + c4 * 4] = v;
    }
    if (t < KT) init_s[t] = g_init[t];
    if (t < KT / 2) ub_s[t] = g_ubase[t];
    __syncthreads();

    // ---- compute: thread = (row, k-pair); lanes 0..15 share kg, vary row ----
    const int r0 = t & (ROWS - 1);    // 0..15
    const int kg = t >> 4;            // 0..31 k-pairs
    const int ub = ub_s[kg];

    const float r4 = 0.92311634638663577f;   // exp(-0.08)
    const unsigned long long R4 =
        (unsigned long long)__float_as_uint(r4) * 0x100000001ULL;  // (r4, r4)

    unsigned long long W2[2], S2[2];
    #pragma unroll
    for (int kk = 0; kk < 2; kk++) {
        float4 p = init_s[kg * 2 + kk];
        W2[kk] = pack2(p.x, p.y);
        S2[kk] = pack2(p.z, p.w);
    }
    unsigned long long acc[2] = {0ULL, 0ULL};

    const ulonglong2* __restrict__ xp = (const ulonglong2*)&x_s[r0 * STRIDE + ub];

    #pragma unroll
    for (int j = 0; j < UJ; j++) {       // 20 x (LDS.128 + 12 packed f32x2 ops)
        ulonglong2 xv = xp[j];           // (x0,x1),(x2,x3)
        #pragma unroll
        for (int kk = 0; kk < 2; kk++) {
            asm("fma.rn.f32x2 %0, %1, %2, %0;" : "+l"(acc[kk]) : "l"(xv.x), "l"(W2[kk]));
            asm("mul.rn.f32x2 %0, %0, %1;"     : "+l"(W2[kk])  : "l"(S2[kk]));
            asm("mul.rn.f32x2 %0, %0, %1;"     : "+l"(S2[kk])  : "l"(R4));
            asm("fma.rn.f32x2 %0, %1, %2, %0;" : "+l"(acc[kk]) : "l"(xv.y), "l"(W2[kk]));
            asm("mul.rn.f32x2 %0, %0, %1;"     : "+l"(W2[kk])  : "l"(S2[kk]));
            asm("mul.rn.f32x2 %0, %0, %1;"     : "+l"(S2[kk])  : "l"(R4));
        }
    }
    __syncthreads();

    // ---- stage outputs in smem (padded), reuse x_s ----
    float* out_s = x_s;
    *(float2*)&out_s[r0 * OSTRIDE + kg * 2] =
        make_float2(hsum2(acc[0]), hsum2(acc[1]));
    __syncthreads();

    // ---- coalesced float2 store: ROWS*KT/2 = 512 float2, one per thread ----
    float2* __restrict__ og = (float2*)(out + tile * (size_t)(ROWS * KT));
    int r2 = t >> 5;       // output row within tile
    int c2 = t & 31;       // float2 column
    og[t] = *(float2*)&out_s[r2 * OSTRIDE + c2 * 2];
}

extern "C" void kernel_launch(void* const* d_in, const int* in_sizes, int n_in,
                              void* d_out, int out_size) {
    const float* x = (const float*)d_in[0];      // [16384, 8192] fp32
    const float* w = (const float*)d_in[1];      // [64] fp32
    float* out = (float*)d_out;                  // [16384, 512] fp32

    precompute_kernel<<<1, KT>>>(w);
    const int n_rows = 16384 * NUM_P;            // 131072 (b,p) rows
    sampling_main_kernel<<<n_rows / ROWS, THREADS>>>(x, out);
}